// round 3
// baseline (speedup 1.0000x reference)
#include <cuda_runtime.h>

#define DD 768
#define Q6 6
#define INV_T 14.285714285714286f
#define CSHIFT 14.285714285714286f

static __device__ float g_S[512];
static __device__ float g_pos[512];
static __device__ float g_mlm_sum;
static __device__ int   g_mlm_cnt;
static __device__ float g_sonnet_sum;
static __device__ int   g_lab64;

__device__ __forceinline__ float wsum(float v) {
    v += __shfl_xor_sync(0xffffffffu, v, 16);
    v += __shfl_xor_sync(0xffffffffu, v, 8);
    v += __shfl_xor_sync(0xffffffffu, v, 4);
    v += __shfl_xor_sync(0xffffffffu, v, 2);
    v += __shfl_xor_sync(0xffffffffu, v, 1);
    return v;
}

// Load this lane's 24 floats of a 768-float row (coalesced float4 pattern:
// float4 index = lane + 32*q), return per-lane partial sum of squares.
__device__ __forceinline__ float load_chunk(const float* __restrict__ row, float* v, int lane) {
    const float4* r4 = (const float4*)row;
    float sq = 0.f;
#pragma unroll
    for (int q = 0; q < Q6; ++q) {
        float4 t = r4[lane + 32 * q];
        v[4*q+0] = t.x; v[4*q+1] = t.y; v[4*q+2] = t.z; v[4*q+3] = t.w;
        sq = fmaf(t.x, t.x, sq); sq = fmaf(t.y, t.y, sq);
        sq = fmaf(t.z, t.z, sq); sq = fmaf(t.w, t.w, sq);
    }
    return sq;
}

// ---------------- init + label-dtype detection ----------------
__global__ void k_init(const void* __restrict__ labels, int nRows, int nA_total) {
    int tid = threadIdx.x;
    for (int i = tid; i < nA_total; i += blockDim.x) { g_S[i] = 0.f; g_pos[i] = 0.f; }
    if (tid == 0) { g_mlm_sum = 0.f; g_mlm_cnt = 0; g_sonnet_sum = 0.f; }
    __shared__ int s_ok;
    if (tid == 0) s_ok = 1;
    __syncthreads();
    // If labels are int64 (little-endian), every odd int32 word is the sign
    // extension: 0 (label >= 0) or -1 (label == -100). For int32 labels the
    // odd words are labels themselves (-100 or [0, V)) -> detection is exact
    // in practice.
    const int* p = (const int*)labels;
    int half = nRows >> 1;
    bool bad = false;
    for (int i = tid; i < half; i += blockDim.x) {
        int hi = p[2 * i + 1];
        if (hi != 0 && hi != -1) bad = true;
    }
    if (bad) s_ok = 0;
    __syncthreads();
    if (tid == 0) g_lab64 = s_ok;
}

// ---------------- role: MLM cross-entropy, one block per row ----------------
__device__ __forceinline__ void mlm_block(const float* __restrict__ logits,
                                          const void* __restrict__ labels,
                                          int row, int V) {
    int lab = g_lab64 ? (int)((const long long*)labels)[row]
                      : ((const int*)labels)[row];
    if (lab < 0) return;  // ignore_index row: zero contribution, skip 122KB read
    const float* x = logits + (size_t)row * V;
    float s0 = 0.f, s1 = 0.f;
    if ((V & 1) == 0 && (((size_t)x & 7) == 0)) {
        const float2* x2 = (const float2*)x;
        int n2 = V >> 1;
#pragma unroll 4
        for (int i = threadIdx.x; i < n2; i += 256) {
            float2 v = x2[i];
            s0 += __expf(v.x);
            s1 += __expf(v.y);
        }
    } else {
        for (int i = threadIdx.x; i < V; i += 256) s0 += __expf(x[i]);
    }
    float s = wsum(s0 + s1);
    __shared__ float sw8[8];
    int w = threadIdx.x >> 5;
    if ((threadIdx.x & 31) == 0) sw8[w] = s;
    __syncthreads();
    if (threadIdx.x == 0) {
        float tot = sw8[0];
#pragma unroll
        for (int i = 1; i < 8; ++i) tot += sw8[i];
        float nll = logf(tot) - x[lab];
        atomicAdd(&g_mlm_sum, nll);
        atomicAdd(&g_mlm_cnt, 1);
    }
}

// ------- role: InfoNCE tile (8 anchors x <=64 negatives per block) -------
__device__ __forceinline__ void infonce_block(const float* __restrict__ A,
                                              const float* __restrict__ Pp,
                                              const float* __restrict__ Ng,
                                              int nP, int nN,
                                              int ga, int gn, int Sbase) {
    __shared__ float inv_nn[64];
    int tid = threadIdx.x, w = tid >> 5, lane = tid & 31;
    int nBase = gn << 6;
    int nCnt = min(64, nN - nBase);
    // inverse norms of this negative tile
    for (int j = w; j < nCnt; j += 8) {
        float tmp[24];
        float sq = wsum(load_chunk(Ng + (size_t)(nBase + j) * DD, tmp, lane));
        if (lane == 0) inv_nn[j] = rsqrtf(fmaxf(sq, 1e-24f));
    }
    __syncthreads();
    int a = ga * 8 + w;
    if (a >= nP) return;  // whole-warp exit; no further block syncs below
    // normalized anchor, resident in registers
    float av[24];
    float sq = wsum(load_chunk(A + (size_t)a * DD, av, lane));
    float inv = rsqrtf(fmaxf(sq, 1e-24f));
#pragma unroll
    for (int i = 0; i < 24; ++i) av[i] *= inv;

    float acc = 0.f;
    for (int j = 0; j < nCnt; ++j) {
        const float4* r4 = (const float4*)(Ng + (size_t)(nBase + j) * DD);
        float d = 0.f;
#pragma unroll
        for (int q = 0; q < Q6; ++q) {
            float4 t = r4[lane + 32 * q];
            d = fmaf(av[4*q+0], t.x, d);
            d = fmaf(av[4*q+1], t.y, d);
            d = fmaf(av[4*q+2], t.z, d);
            d = fmaf(av[4*q+3], t.w, d);
        }
        d = wsum(d);
        // sim <= 1/T always, so exp(sim - C) <= 1: no online max needed
        acc += __expf(fmaf(d, inv_nn[j] * INV_T, -CSHIFT));
    }
    if (gn == 0) {  // positive term handled once per anchor
        float pv[24];
        float psq = wsum(load_chunk(Pp + (size_t)a * DD, pv, lane));
        float dp = 0.f;
#pragma unroll
        for (int i = 0; i < 24; ++i) dp = fmaf(pv[i], av[i], dp);
        dp = wsum(dp);
        float pos = dp * rsqrtf(fmaxf(psq, 1e-24f)) * INV_T;
        acc += __expf(pos - CSHIFT);
        if (lane == 0) g_pos[Sbase + a] = pos;
    }
    if (lane == 0) atomicAdd(&g_S[Sbase + a], acc);
}

// ---------------- role: sonnet self-similarity (single block) ----------------
__device__ __forceinline__ void sonnet_block(const float* __restrict__ E, int Bs) {
    __shared__ float invn[32];
    int tid = threadIdx.x, w = tid >> 5, lane = tid & 31;
    for (int i = w; i < Bs; i += 8) {
        float tmp[24];
        float sq = wsum(load_chunk(E + (size_t)i * DD, tmp, lane));
        if (lane == 0) invn[i] = rsqrtf(fmaxf(sq, 1e-24f));
    }
    __syncthreads();
    for (int i = w; i < Bs; i += 8) {
        float xv[24];
        load_chunk(E + (size_t)i * DD, xv, lane);
        float si = invn[i];
        float acc = 0.f, diag = 0.f;
        for (int j = 0; j < Bs; ++j) {
            const float4* r4 = (const float4*)(E + (size_t)j * DD);
            float d = 0.f;
#pragma unroll
            for (int q = 0; q < Q6; ++q) {
                float4 t = r4[lane + 32 * q];
                d = fmaf(xv[4*q+0], t.x, d);
                d = fmaf(xv[4*q+1], t.y, d);
                d = fmaf(xv[4*q+2], t.z, d);
                d = fmaf(xv[4*q+3], t.w, d);
            }
            d = wsum(d);
            float sim = d * si * invn[j] * INV_T;
            acc += __expf(sim - CSHIFT);
            if (j == i) diag = sim;
        }
        if (lane == 0) atomicAdd(&g_sonnet_sum, logf(acc) + CSHIFT - diag);
    }
}

// ---------------- fused main kernel ----------------
__global__ void __launch_bounds__(256)
k_main(const float* __restrict__ logits, const void* __restrict__ labels,
       int nRows, int V,
       const float* __restrict__ lA, const float* __restrict__ lP,
       const float* __restrict__ lN, int PL, int NL, int LA, int LN,
       const float* __restrict__ qA, const float* __restrict__ qP,
       const float* __restrict__ qN, int PQ, int NQ, int QA, int QN,
       const float* __restrict__ sE, int Bs) {
    int b = blockIdx.x;
    if (b < nRows) { mlm_block(logits, labels, b, V); return; }
    b -= nRows;
    if (b < LA * LN) { infonce_block(lA, lP, lN, PL, NL, b / LN, b % LN, 0); return; }
    b -= LA * LN;
    if (b < QA * QN) { infonce_block(qA, qP, qN, PQ, NQ, b / QN, b % QN, PL); return; }
    sonnet_block(sE, Bs);
}

// ---------------- finalize ----------------
__global__ void k_fin(float* __restrict__ out, int PL, int PQ,
                      float invPL, float invPQ, int Bs) {
    __shared__ float red[512];
    int tid = threadIdx.x;
    float acc = 0.f;
    for (int i = tid; i < PL + PQ; i += 512) {
        float wgt = (i < PL) ? (0.2f * invPL) : (0.2f * invPQ);
        acc += wgt * (logf(g_S[i]) + CSHIFT - g_pos[i]);
    }
    red[tid] = acc;
    __syncthreads();
    for (int s = 256; s; s >>= 1) {
        if (tid < s) red[tid] += red[tid + s];
        __syncthreads();
    }
    if (tid == 0) {
        int c = g_mlm_cnt; if (c < 1) c = 1;
        float mlm = g_mlm_sum / (float)c;
        out[0] = 0.5f * mlm + red[0] + 0.1f * g_sonnet_sum / (float)Bs;
    }
}

extern "C" void kernel_launch(void* const* d_in, const int* in_sizes, int n_in,
                              void* d_out, int out_size) {
    const float* logits = (const float*)d_in[0];
    const void*  labels = d_in[1];
    const float* lA = (const float*)d_in[2];
    const float* lP = (const float*)d_in[3];
    const float* lN = (const float*)d_in[4];
    const float* qA = (const float*)d_in[5];
    const float* qP = (const float*)d_in[6];
    const float* qN = (const float*)d_in[7];
    const float* sE = (const float*)d_in[8];

    int nRows = in_sizes[1];
    int V  = in_sizes[0] / nRows;
    int PL = in_sizes[2] / DD, NL = in_sizes[4] / DD;
    int PQ = in_sizes[5] / DD, NQ = in_sizes[7] / DD;
    int Bs = in_sizes[8] / DD;

    int LA = (PL + 7) / 8,  LN = (NL + 63) / 64;
    int QA = (PQ + 7) / 8,  QN = (NQ + 63) / 64;

    k_init<<<1, 256>>>(labels, nRows, PL + PQ);
    int grid = nRows + LA * LN + QA * QN + 1;
    k_main<<<grid, 256>>>(logits, labels, nRows, V,
                          lA, lP, lN, PL, NL, LA, LN,
                          qA, qP, qN, PQ, NQ, QA, QN,
                          sE, Bs);
    k_fin<<<1, 512>>>((float*)d_out, PL, PQ, 1.0f / PL, 1.0f / PQ, Bs);
}